// round 15
// baseline (speedup 1.0000x reference)
#include <cuda_runtime.h>
#include <cuda_fp16.h>
#include <stdint.h>
#include <math.h>

#define F_IN 128
#define HID  16
#define NC   10
#define CP   12
#define N_MAX 100000
#define E_MAX 1600000

// ---------------- scratch (allocation-free, aligned) ----------------
// interleaved fp16 tables: per node 64B block; half[2j]=a0[j], half[2j+1]=ad[j]
__device__ __align__(16) __half g_aqh[N_MAX * 32];
// per node: pairs (b0[c], bd[c]) c=0..11 in halves 0..23, rest pad (48B used)
__device__ __align__(16) __half g_bqh[N_MAX * 32];
__device__ __align__(16) float g_base1[N_MAX * HID];  // x @ root1 + b1
__device__ __align__(16) float g_agg1 [N_MAX * HID];
__device__ __align__(16) float g_deg  [N_MAX];
__device__ __align__(16) float g_base2[N_MAX * CP];   // h @ root2 + b2
__device__ __align__(16) float g_agg2 [N_MAX * CP];

static __device__ __forceinline__ unsigned int pack_h2(float a, float b) {
    __half2 h = __floats2half2_rn(a, b);
    return *reinterpret_cast<unsigned int*>(&h);
}

// ---------------- layer-1 node transform: 2 threads/node ---------------------
// thread r in {0,1} computes output channels j in [r*8, r*8+8) of a0/ad/root
__global__ __launch_bounds__(256)
void node1_kernel(const float* __restrict__ x,
                  const float* __restrict__ W1,
                  const float* __restrict__ root1,
                  const float* __restrict__ b1, int N)
{
    __shared__ float sW0[F_IN * HID];
    __shared__ float sWd[F_IN * HID];
    __shared__ float sR [F_IN * HID];
    for (int i = threadIdx.x; i < F_IN * HID; i += blockDim.x) {
        float w0 = W1[i];
        sW0[i] = w0;
        sWd[i] = W1[F_IN * HID + i] - w0;
        sR [i] = root1[i];
    }
    __syncthreads();

    int t = blockIdx.x * blockDim.x + threadIdx.x;
    int n = t >> 1;
    int r = t & 1;
    if (n >= N) return;

    // zero accumulators, split across the pair
    float4 z4 = make_float4(0.f, 0.f, 0.f, 0.f);
    if (r == 0) {
#pragma unroll
        for (int j4 = 0; j4 < HID / 4; j4++)
            *reinterpret_cast<float4*>(&g_agg1[(size_t)n * HID + j4 * 4]) = z4;
    } else {
#pragma unroll
        for (int c4 = 0; c4 < CP / 4; c4++)
            *reinterpret_cast<float4*>(&g_agg2[(size_t)n * CP + c4 * 4]) = z4;
        g_deg[n] = 0.f;
    }

    float acc0[8], accd[8], accr[8];
#pragma unroll
    for (int j = 0; j < 8; j++) { acc0[j] = 0.f; accd[j] = 0.f; accr[j] = 0.f; }

    const float4* xr = reinterpret_cast<const float4*>(x + (size_t)n * F_IN);
    int joff = r * 8;
#pragma unroll 4
    for (int k4 = 0; k4 < F_IN / 4; k4++) {
        float4 xv = __ldg(&xr[k4]);
        float xs[4] = { xv.x, xv.y, xv.z, xv.w };
#pragma unroll
        for (int kk = 0; kk < 4; kk++) {
            float xk  = xs[kk];
            int  base = (k4 * 4 + kk) * HID + joff;
#pragma unroll
            for (int j4 = 0; j4 < 2; j4++) {
                float4 w0 = *reinterpret_cast<const float4*>(&sW0[base + j4 * 4]);
                float4 wd = *reinterpret_cast<const float4*>(&sWd[base + j4 * 4]);
                float4 wr = *reinterpret_cast<const float4*>(&sR [base + j4 * 4]);
                acc0[j4*4+0] += xk * w0.x; acc0[j4*4+1] += xk * w0.y;
                acc0[j4*4+2] += xk * w0.z; acc0[j4*4+3] += xk * w0.w;
                accd[j4*4+0] += xk * wd.x; accd[j4*4+1] += xk * wd.y;
                accd[j4*4+2] += xk * wd.z; accd[j4*4+3] += xk * wd.w;
                accr[j4*4+0] += xk * wr.x; accr[j4*4+1] += xk * wr.y;
                accr[j4*4+2] += xk * wr.z; accr[j4*4+3] += xk * wr.w;
            }
        }
    }
    // interleaved pack: halves 2j..2j+1 = (a0[j], ad[j]); this thread owns
    // halves [r*16, r*16+16) = two uint4
    uint4 u0, u1;
    u0.x = pack_h2(acc0[0], accd[0]);  u0.y = pack_h2(acc0[1], accd[1]);
    u0.z = pack_h2(acc0[2], accd[2]);  u0.w = pack_h2(acc0[3], accd[3]);
    u1.x = pack_h2(acc0[4], accd[4]);  u1.y = pack_h2(acc0[5], accd[5]);
    u1.z = pack_h2(acc0[6], accd[6]);  u1.w = pack_h2(acc0[7], accd[7]);
    uint4* dst = reinterpret_cast<uint4*>(&g_aqh[(size_t)n * 32 + r * 16]);
    dst[0] = u0; dst[1] = u1;

#pragma unroll
    for (int j4 = 0; j4 < 2; j4++) {
        *reinterpret_cast<float4*>(&g_base1[(size_t)n * HID + joff + j4 * 4]) =
            make_float4(accr[j4*4]   + b1[joff + j4*4],
                        accr[j4*4+1] + b1[joff + j4*4+1],
                        accr[j4*4+2] + b1[joff + j4*4+2],
                        accr[j4*4+3] + b1[joff + j4*4+3]);
    }
}

// ---------------- layer-1 edge pass: 4 lanes/edge, 2 edges/thread (MLP=2) ----
__global__ void edge1_kernel(const int* __restrict__ ei,
                             const float* __restrict__ attr, int E, int Eh)
{
    int t   = blockIdx.x * blockDim.x + threadIdx.x;
    int idx = t >> 2;
    int r   = t & 3;
    if (idx >= Eh) return;
    int e0 = idx;
    int e1 = idx + Eh;
    bool has1 = (e1 < E);

    int   s0 = __ldg(&ei[e0]);
    int   d0 = __ldg(&ei[E + e0]);
    float w0 = __ldg(&attr[e0]);
    int   s1 = has1 ? __ldg(&ei[e1])     : 0;
    int   d1 = has1 ? __ldg(&ei[E + e1]) : 0;
    float w1 = has1 ? __ldg(&attr[e1])   : 0.f;

    uint4 ga = __ldg(reinterpret_cast<const uint4*>(&g_aqh[(size_t)s0 * 32 + r * 8]));
    uint4 gb = has1 ? __ldg(reinterpret_cast<const uint4*>(&g_aqh[(size_t)s1 * 32 + r * 8]))
                    : make_uint4(0u, 0u, 0u, 0u);

    {
        float2 p0 = __half22float2(*reinterpret_cast<__half2*>(&ga.x));
        float2 p1 = __half22float2(*reinterpret_cast<__half2*>(&ga.y));
        float2 p2 = __half22float2(*reinterpret_cast<__half2*>(&ga.z));
        float2 p3 = __half22float2(*reinterpret_cast<__half2*>(&ga.w));
        float4 msg = make_float4(fmaf(w0, p0.y, p0.x), fmaf(w0, p1.y, p1.x),
                                 fmaf(w0, p2.y, p2.x), fmaf(w0, p3.y, p3.x));
        float* dstp = &g_agg1[(size_t)d0 * HID + r * 4];
        asm volatile("red.global.add.v4.f32 [%0], {%1,%2,%3,%4};"
                     :: "l"(dstp), "f"(msg.x), "f"(msg.y), "f"(msg.z), "f"(msg.w)
                     : "memory");
        if (r == 0) atomicAdd(&g_deg[d0], 1.0f);
    }
    if (has1) {
        float2 p0 = __half22float2(*reinterpret_cast<__half2*>(&gb.x));
        float2 p1 = __half22float2(*reinterpret_cast<__half2*>(&gb.y));
        float2 p2 = __half22float2(*reinterpret_cast<__half2*>(&gb.z));
        float2 p3 = __half22float2(*reinterpret_cast<__half2*>(&gb.w));
        float4 msg = make_float4(fmaf(w1, p0.y, p0.x), fmaf(w1, p1.y, p1.x),
                                 fmaf(w1, p2.y, p2.x), fmaf(w1, p3.y, p3.x));
        float* dstp = &g_agg1[(size_t)d1 * HID + r * 4];
        asm volatile("red.global.add.v4.f32 [%0], {%1,%2,%3,%4};"
                     :: "l"(dstp), "f"(msg.x), "f"(msg.y), "f"(msg.z), "f"(msg.w)
                     : "memory");
        if (r == 0) atomicAdd(&g_deg[d1], 1.0f);
    }
}

// ------ layer-1 finalize + ELU + layer-2 node transform: 2 threads/node ------
// both threads of a pair compute h[16]; r=0 emits channels 0..7, r=1 emits 8..11
__global__ __launch_bounds__(256)
void node2_kernel(const float* __restrict__ W2,
                  const float* __restrict__ root2,
                  const float* __restrict__ b2, int N)
{
    __shared__ float sB0[HID * CP];
    __shared__ float sBd[HID * CP];
    __shared__ float sR [HID * CP];
    __shared__ float sb2[CP];
    for (int i = threadIdx.x; i < HID * CP; i += blockDim.x) {
        int j = i / CP, c = i - j * CP;
        float w0 = (c < NC) ? W2[j * NC + c] : 0.f;
        float w1 = (c < NC) ? W2[HID * NC + j * NC + c] : 0.f;
        sB0[i] = w0;
        sBd[i] = w1 - w0;
        sR [i] = (c < NC) ? root2[j * NC + c] : 0.f;
    }
    if (threadIdx.x < CP) sb2[threadIdx.x] = (threadIdx.x < NC) ? b2[threadIdx.x] : 0.f;
    __syncthreads();

    int t = blockIdx.x * blockDim.x + threadIdx.x;
    int n = t >> 1;
    int r = t & 1;
    if (n >= N) return;

    float inv = 1.f / fmaxf(g_deg[n], 1.f);
    float h[HID];
#pragma unroll
    for (int j4 = 0; j4 < HID / 4; j4++) {
        float4 ag = *reinterpret_cast<const float4*>(&g_agg1 [(size_t)n * HID + j4 * 4]);
        float4 bs = *reinterpret_cast<const float4*>(&g_base1[(size_t)n * HID + j4 * 4]);
        float v[4] = { ag.x * inv + bs.x, ag.y * inv + bs.y,
                       ag.z * inv + bs.z, ag.w * inv + bs.w };
#pragma unroll
        for (int q = 0; q < 4; q++)
            h[j4 * 4 + q] = (v[q] > 0.f) ? v[q] : expm1f(v[q]);
    }

    // r=0 -> c4 groups {0,1} (channels 0..7); r=1 -> c4 group {2} (channels 8..11)
    int c4beg = (r == 0) ? 0 : 2;
    int c4end = (r == 0) ? 2 : 3;
    float o0[8], od[8], orr[8];
#pragma unroll
    for (int c = 0; c < 8; c++) { o0[c] = 0.f; od[c] = 0.f; orr[c] = 0.f; }
#pragma unroll
    for (int j = 0; j < HID; j++) {
        float hj = h[j];
        for (int c4 = c4beg, q = 0; c4 < c4end; c4++, q++) {
            float4 w0 = *reinterpret_cast<const float4*>(&sB0[j * CP + c4 * 4]);
            float4 wd = *reinterpret_cast<const float4*>(&sBd[j * CP + c4 * 4]);
            float4 wr = *reinterpret_cast<const float4*>(&sR [j * CP + c4 * 4]);
            o0[q*4+0] += hj * w0.x; o0[q*4+1] += hj * w0.y;
            o0[q*4+2] += hj * w0.z; o0[q*4+3] += hj * w0.w;
            od[q*4+0] += hj * wd.x; od[q*4+1] += hj * wd.y;
            od[q*4+2] += hj * wd.z; od[q*4+3] += hj * wd.w;
            orr[q*4+0] += hj * wr.x; orr[q*4+1] += hj * wr.y;
            orr[q*4+2] += hj * wr.z; orr[q*4+3] += hj * wr.w;
        }
    }

    // pack this thread's channels: halves [c4beg*8 .. ) with (b0,bd) interleaved
    __half* blk = &g_bqh[(size_t)n * 32];
    for (int c4 = c4beg, q = 0; c4 < c4end; c4++, q++) {
        uint4 u;
        u.x = pack_h2(o0[q*4+0], od[q*4+0]);
        u.y = pack_h2(o0[q*4+1], od[q*4+1]);
        u.z = pack_h2(o0[q*4+2], od[q*4+2]);
        u.w = pack_h2(o0[q*4+3], od[q*4+3]);
        *reinterpret_cast<uint4*>(blk + c4 * 8) = u;

        *reinterpret_cast<float4*>(&g_base2[(size_t)n * CP + c4 * 4]) =
            make_float4(orr[q*4+0] + sb2[c4*4+0], orr[q*4+1] + sb2[c4*4+1],
                        orr[q*4+2] + sb2[c4*4+2], orr[q*4+3] + sb2[c4*4+3]);
    }
}

// ---------------- layer-2 edge pass: 3 lanes/edge, 2 edges/thread (MLP=2) ----
__global__ void edge2_kernel(const int* __restrict__ ei,
                             const float* __restrict__ attr, int E, int Eh)
{
    int t    = blockIdx.x * blockDim.x + threadIdx.x;
    int warp = t >> 5;
    int lane = t & 31;
    if (lane >= 30) return;
    int el = lane / 3;                // 0..9
    int r  = lane - el * 3;           // 0..2
    int e0 = warp * 10 + el;
    if (e0 >= Eh) return;
    int e1 = e0 + Eh;
    bool has1 = (e1 < E);

    int   s0 = __ldg(&ei[e0]);
    int   d0 = __ldg(&ei[E + e0]);
    float w0 = __ldg(&attr[e0]);
    int   s1 = has1 ? __ldg(&ei[e1])     : 0;
    int   d1 = has1 ? __ldg(&ei[E + e1]) : 0;
    float w1 = has1 ? __ldg(&attr[e1])   : 0.f;

    uint4 ga = __ldg(reinterpret_cast<const uint4*>(&g_bqh[(size_t)s0 * 32 + r * 8]));
    uint4 gb = has1 ? __ldg(reinterpret_cast<const uint4*>(&g_bqh[(size_t)s1 * 32 + r * 8]))
                    : make_uint4(0u, 0u, 0u, 0u);

    {
        float2 p0 = __half22float2(*reinterpret_cast<__half2*>(&ga.x));
        float2 p1 = __half22float2(*reinterpret_cast<__half2*>(&ga.y));
        float2 p2 = __half22float2(*reinterpret_cast<__half2*>(&ga.z));
        float2 p3 = __half22float2(*reinterpret_cast<__half2*>(&ga.w));
        float4 msg = make_float4(fmaf(w0, p0.y, p0.x), fmaf(w0, p1.y, p1.x),
                                 fmaf(w0, p2.y, p2.x), fmaf(w0, p3.y, p3.x));
        float* dstp = &g_agg2[(size_t)d0 * CP + r * 4];
        asm volatile("red.global.add.v4.f32 [%0], {%1,%2,%3,%4};"
                     :: "l"(dstp), "f"(msg.x), "f"(msg.y), "f"(msg.z), "f"(msg.w)
                     : "memory");
    }
    if (has1) {
        float2 p0 = __half22float2(*reinterpret_cast<__half2*>(&gb.x));
        float2 p1 = __half22float2(*reinterpret_cast<__half2*>(&gb.y));
        float2 p2 = __half22float2(*reinterpret_cast<__half2*>(&gb.z));
        float2 p3 = __half22float2(*reinterpret_cast<__half2*>(&gb.w));
        float4 msg = make_float4(fmaf(w1, p0.y, p0.x), fmaf(w1, p1.y, p1.x),
                                 fmaf(w1, p2.y, p2.x), fmaf(w1, p3.y, p3.x));
        float* dstp = &g_agg2[(size_t)d1 * CP + r * 4];
        asm volatile("red.global.add.v4.f32 [%0], {%1,%2,%3,%4};"
                     :: "l"(dstp), "f"(msg.x), "f"(msg.y), "f"(msg.z), "f"(msg.w)
                     : "memory");
    }
}

// ---------------- output: 4 lanes/node (r<3 active), v4 loads ----------------
__global__ void out_kernel(float* __restrict__ out, int N)
{
    int t = blockIdx.x * blockDim.x + threadIdx.x;
    int n = t >> 2;
    int r = t & 3;
    if (n >= N || r == 3) return;

    float inv = 1.f / fmaxf(g_deg[n], 1.f);
    float4 ag = *reinterpret_cast<const float4*>(&g_agg2 [(size_t)n * CP + r * 4]);
    float4 bs = *reinterpret_cast<const float4*>(&g_base2[(size_t)n * CP + r * 4]);
    float o[4] = { ag.x * inv + bs.x, ag.y * inv + bs.y,
                   ag.z * inv + bs.z, ag.w * inv + bs.w };

    float* op = out + (size_t)n * NC + r * 4;
    int lim = NC - r * 4;                 // 4,4,2 for r=0,1,2
#pragma unroll
    for (int q = 0; q < 4; q++)
        if (q < lim) op[q] = o[q];
}

// ---------------- launcher ----------------
extern "C" void kernel_launch(void* const* d_in, const int* in_sizes, int n_in,
                              void* d_out, int out_size)
{
    const float* x     = (const float*)d_in[0];
    const int*   ei    = (const int*)d_in[1];
    const float* attr  = (const float*)d_in[2];
    const float* W1    = (const float*)d_in[3];
    const float* root1 = (const float*)d_in[4];
    const float* b1    = (const float*)d_in[5];
    const float* W2    = (const float*)d_in[6];
    const float* root2 = (const float*)d_in[7];
    const float* b2    = (const float*)d_in[8];
    float*       out   = (float*)d_out;

    int N  = in_sizes[0] / F_IN;
    int E  = in_sizes[2];
    int Eh = (E + 1) / 2;

    node1_kernel<<<(N * 2 + 255) / 256, 256>>>(x, W1, root1, b1, N);

    long long t1 = (long long)Eh * 4;
    edge1_kernel<<<(unsigned)((t1 + 255) / 256), 256>>>(ei, attr, E, Eh);

    node2_kernel<<<(N * 2 + 255) / 256, 256>>>(W2, root2, b2, N);

    long long nwarps = ((long long)Eh + 9) / 10;
    long long t2 = nwarps * 32;
    edge2_kernel<<<(unsigned)((t2 + 255) / 256), 256>>>(ei, attr, E, Eh);

    out_kernel<<<(N * 4 + 255) / 256, 256>>>(out, N);
}